// round 3
// baseline (speedup 1.0000x reference)
#include <cuda_runtime.h>

#define BB  32
#define TT  128
#define KK  32
#define HH  4
#define KH  128   // K*H
#define HID 256
#define DIN 160   // K*H + K

// Static scratch (no allocations allowed in kernel_launch)
__device__ float g_q[BB*TT*KH];
__device__ float g_k[BB*TT*KH];
__device__ float g_v[BB*TT*KH];
__device__ float g_att[BB*TT*KH];

// ---------------------------------------------------------------------------
// Kernel 1: q = state@Wq, sk = state@Wk, sv = state@Wv
// grid (B, 3 matrices), 128 threads: thread = output col j, loops all 128 rows.
// smem: one 32x128 weight (16KB) + this batch's 128x32 state (16KB) = 32KB.
// ---------------------------------------------------------------------------
__global__ void proj_kernel(const float* __restrict__ state,
                            const float* __restrict__ Wq,
                            const float* __restrict__ Wk,
                            const float* __restrict__ Wv) {
    __shared__ float sW[KK*KH];   // 16KB
    __shared__ float sS[TT*KK];   // 16KB
    int b = blockIdx.x, m = blockIdx.y;
    int tid = threadIdx.x;        // 128

    const float* W = (m == 0) ? Wq : (m == 1) ? Wk : Wv;
    float* dst     = (m == 0) ? g_q : (m == 1) ? g_k : g_v;

    for (int i = tid; i < KK*KH; i += TT) sW[i] = W[i];
    for (int i = tid; i < TT*KK; i += TT) sS[i] = state[b*TT*KK + i];
    __syncthreads();

    int j = tid;                  // output column 0..127
    for (int r = 0; r < TT; r += 4) {
        float a0 = 0.f, a1 = 0.f, a2 = 0.f, a3 = 0.f;
        #pragma unroll
        for (int i = 0; i < KK; i++) {
            float w = sW[i*KH + j];
            a0 = fmaf(sS[(r+0)*KK + i], w, a0);
            a1 = fmaf(sS[(r+1)*KK + i], w, a1);
            a2 = fmaf(sS[(r+2)*KK + i], w, a2);
            a3 = fmaf(sS[(r+3)*KK + i], w, a3);
        }
        dst[(b*TT + r+0)*KH + j] = a0;
        dst[(b*TT + r+1)*KH + j] = a1;
        dst[(b*TT + r+2)*KH + j] = a2;
        dst[(b*TT + r+3)*KH + j] = a3;
    }
}

// ---------------------------------------------------------------------------
// Kernel 2: attention per (b,h). logits = q_i . sk_j / sqrt(K), mask j==i,
// online softmax, att_i = sum_j w_j sv_j - sv_i.
// grid (B, H), 128 threads, one thread per query row i.
// ---------------------------------------------------------------------------
__global__ void attn_kernel() {
    __shared__ float sk[TT*KK];   // 16KB
    __shared__ float sv[TT*KK];   // 16KB
    int b = blockIdx.x, h = blockIdx.y;
    int i = threadIdx.x;          // query index 0..127

    // cooperative load of this (b,h)'s key/value slabs
    for (int idx = i; idx < TT*KK; idx += TT) {
        int t = idx >> 5, c = idx & 31;
        sk[idx] = g_k[(b*TT + t)*KH + h*KK + c];
        sv[idx] = g_v[(b*TT + t)*KH + h*KK + c];
    }

    float q[KK];
    #pragma unroll
    for (int c = 0; c < KK; c++) q[c] = g_q[(b*TT + i)*KH + h*KK + c];
    __syncthreads();

    const float scale = rsqrtf((float)KK);
    float mrun = -1e30f, denom = 0.f;
    float acc[KK];
    #pragma unroll
    for (int c = 0; c < KK; c++) acc[c] = 0.f;

    for (int j = 0; j < TT; j++) {
        if (j == i) continue;     // self is masked out of the neighbor set
        float l = 0.f;
        #pragma unroll
        for (int c = 0; c < KK; c++) l = fmaf(q[c], sk[j*KK + c], l);
        l *= scale;
        float mn   = fmaxf(mrun, l);
        float corr = __expf(mrun - mn);
        float p    = __expf(l - mn);
        denom = denom * corr + p;
        #pragma unroll
        for (int c = 0; c < KK; c++)
            acc[c] = fmaf(acc[c], corr, p * sv[j*KK + c]);
        mrun = mn;
    }

    float inv = 1.f / denom;
    #pragma unroll
    for (int c = 0; c < KK; c++)
        g_att[(b*TT + i)*KH + h*KK + c] = acc[c] * inv - sv[i*KK + c];
}

// ---------------------------------------------------------------------------
// Kernel 3: MLP. x = [att | state] (160) -> relu(x@W1+b1) -> relu(@W2+b2) -> @Wo+bo
// 16 rows per block (amortize weight reads), 256 threads = one per hidden unit.
// ---------------------------------------------------------------------------
__global__ void mlp_kernel(const float* __restrict__ state,
                           const float* __restrict__ W1, const float* __restrict__ b1,
                           const float* __restrict__ W2, const float* __restrict__ b2,
                           const float* __restrict__ Wo, const float* __restrict__ bo,
                           float* __restrict__ out) {
    const int R = 16;
    __shared__ float xs[R][DIN];   // 10KB
    __shared__ float hs[R][HID];   // 16KB
    int row0 = blockIdx.x * R;
    int tid  = threadIdx.x;        // 256

    for (int idx = tid; idx < R*KH; idx += 256) {
        int r = idx >> 7, c = idx & 127;
        xs[r][c] = g_att[(row0 + r)*KH + c];
    }
    for (int idx = tid; idx < R*KK; idx += 256) {
        int r = idx >> 5, c = idx & 31;
        xs[r][KH + c] = state[(row0 + r)*KK + c];
    }
    __syncthreads();

    // layer 1: each thread computes hidden unit `tid` for all 16 rows
    float acc[R];
    float bias1 = b1[tid];
    #pragma unroll
    for (int r = 0; r < R; r++) acc[r] = bias1;
    for (int i = 0; i < DIN; i++) {
        float w = W1[i*HID + tid];
        #pragma unroll
        for (int r = 0; r < R; r++) acc[r] = fmaf(xs[r][i], w, acc[r]);
    }
    #pragma unroll
    for (int r = 0; r < R; r++) hs[r][tid] = fmaxf(acc[r], 0.f);
    __syncthreads();

    // layer 2
    float acc2[R];
    float bias2 = b2[tid];
    #pragma unroll
    for (int r = 0; r < R; r++) acc2[r] = bias2;
    for (int i = 0; i < HID; i++) {
        float w = W2[i*HID + tid];
        #pragma unroll
        for (int r = 0; r < R; r++) acc2[r] = fmaf(hs[r][i], w, acc2[r]);
    }
    __syncthreads();

    // output: relu(h2) * Wo[tid], then row-wise reduce over 256 units
    float wo = Wo[tid];
    #pragma unroll
    for (int r = 0; r < R; r++) hs[r][tid] = fmaxf(acc2[r], 0.f) * wo;
    __syncthreads();

    int w = tid >> 5, lane = tid & 31;
    float bov = bo[0];
    #pragma unroll
    for (int rr = 0; rr < 2; rr++) {
        int r = w*2 + rr;
        float s = 0.f;
        #pragma unroll
        for (int c = 0; c < HID/32; c++) s += hs[r][lane + c*32];
        #pragma unroll
        for (int off = 16; off; off >>= 1)
            s += __shfl_xor_sync(0xffffffffu, s, off);
        if (lane == 0) out[row0 + r] = s + bov;
    }
}

// ---------------------------------------------------------------------------
extern "C" void kernel_launch(void* const* d_in, const int* in_sizes, int n_in,
                              void* d_out, int out_size) {
    const float* state = (const float*)d_in[0];
    const float* Wq    = (const float*)d_in[1];
    const float* Wk    = (const float*)d_in[2];
    const float* Wv    = (const float*)d_in[3];
    const float* W1    = (const float*)d_in[4];
    const float* b1    = (const float*)d_in[5];
    const float* W2    = (const float*)d_in[6];
    const float* b2    = (const float*)d_in[7];
    const float* Wo    = (const float*)d_in[8];
    const float* bo    = (const float*)d_in[9];
    float* out = (float*)d_out;

    proj_kernel<<<dim3(BB, 3), TT>>>(state, Wq, Wk, Wv);
    attn_kernel<<<dim3(BB, HH), TT>>>();
    mlp_kernel<<<(BB*TT)/16, 256>>>(state, W1, b1, W2, b2, Wo, bo, out);
}

// round 5
// speedup vs baseline: 1.4375x; 1.4375x over previous
#include <cuda_runtime.h>

#define BB  32
#define TT  128
#define KK  32
#define HH  4
#define KH  128   // K*H
#define HID 256
#define DIN 160   // K*H + K

// Static scratch (no allocations allowed in kernel_launch)
__device__ float g_q[BB*TT*KH];
__device__ float g_k[BB*TT*KH];
__device__ float g_v[BB*TT*KH];
__device__ float g_att[BB*TT*KH];

// ---------------------------------------------------------------------------
// Kernel 1: q = state@Wq, sk = state@Wk, sv = state@Wv
// grid (B, 3 matrices, 4 row-chunks), 128 threads = one output column each.
// Weight column lives in registers; state rows broadcast from smem as float4.
// ---------------------------------------------------------------------------
__global__ void __launch_bounds__(128) proj_kernel(
        const float* __restrict__ state,
        const float* __restrict__ Wq,
        const float* __restrict__ Wk,
        const float* __restrict__ Wv) {
    __shared__ float sW[KK*KH];    // 16KB
    __shared__ float sS[32*KK];    // 4KB (32-row chunk)
    int b = blockIdx.x, m = blockIdx.y, ch = blockIdx.z;
    int tid = threadIdx.x;         // 128

    const float* W = (m == 0) ? Wq : (m == 1) ? Wk : Wv;
    float* dst     = (m == 0) ? g_q : (m == 1) ? g_k : g_v;

    // cooperative loads (float4, coalesced)
    {
        const float4* Wsrc = (const float4*)W;
        float4* Wdst = (float4*)sW;
        #pragma unroll
        for (int i = 0; i < (KK*KH/4)/128; i++)
            Wdst[tid + i*128] = Wsrc[tid + i*128];
        const float4* Ssrc = (const float4*)(state + (b*TT + ch*32)*KK);
        float4* Sdst = (float4*)sS;
        #pragma unroll
        for (int i = 0; i < (32*KK/4)/128; i++)
            Sdst[tid + i*128] = Ssrc[tid + i*128];
    }
    __syncthreads();

    // weight column j -> registers
    float w[KK];
    #pragma unroll
    for (int i = 0; i < KK; i++) w[i] = sW[i*KH + tid];

    const float4* sS4 = (const float4*)sS;
    float* outp = dst + (b*TT + ch*32)*KH + tid;

    #pragma unroll 2
    for (int r = 0; r < 32; r += 4) {
        float a0 = 0.f, a1 = 0.f, a2 = 0.f, a3 = 0.f;
        #pragma unroll
        for (int i4 = 0; i4 < KK/4; i4++) {
            float4 x0 = sS4[(r+0)*(KK/4) + i4];
            float4 x1 = sS4[(r+1)*(KK/4) + i4];
            float4 x2 = sS4[(r+2)*(KK/4) + i4];
            float4 x3 = sS4[(r+3)*(KK/4) + i4];
            int i = i4*4;
            a0 = fmaf(x0.x, w[i], fmaf(x0.y, w[i+1], fmaf(x0.z, w[i+2], fmaf(x0.w, w[i+3], a0))));
            a1 = fmaf(x1.x, w[i], fmaf(x1.y, w[i+1], fmaf(x1.z, w[i+2], fmaf(x1.w, w[i+3], a1))));
            a2 = fmaf(x2.x, w[i], fmaf(x2.y, w[i+1], fmaf(x2.z, w[i+2], fmaf(x2.w, w[i+3], a2))));
            a3 = fmaf(x3.x, w[i], fmaf(x3.y, w[i+1], fmaf(x3.z, w[i+2], fmaf(x3.w, w[i+3], a3))));
        }
        outp[(r+0)*KH] = a0;
        outp[(r+1)*KH] = a1;
        outp[(r+2)*KH] = a2;
        outp[(r+3)*KH] = a3;
    }
}

// ---------------------------------------------------------------------------
// Kernel 2: attention per (b,h). 256 threads: two threads per query split
// the j-range [0,64)/[64,128), each runs online softmax, then 2-way merge.
// att_i = sum_j w_j sv_j - sv_i  (softmax over j != i).
// ---------------------------------------------------------------------------
__global__ void __launch_bounds__(256) attn_kernel() {
    __shared__ float sk[TT*KK];   // 16KB  (reused as merge acc buffer)
    __shared__ float sv[TT*KK];   // 16KB
    __shared__ float sm2[TT];
    __shared__ float sd2[TT];
    int b = blockIdx.x, h = blockIdx.y;
    int tid = threadIdx.x;        // 256
    int i = tid & 127;            // query index
    int half = tid >> 7;          // j-range half

    // cooperative load of this (b,h)'s key/value slabs (float4, coalesced)
    {
        const float4* k4 = (const float4*)g_k;
        const float4* v4 = (const float4*)g_v;
        float4* skd = (float4*)sk;
        float4* svd = (float4*)sv;
        #pragma unroll
        for (int it = 0; it < (TT*KK/4)/256; it++) {
            int v = tid + it*256;         // float4 index in [0,1024)
            int t = v >> 3, cc = v & 7;   // row, float4-within-row
            int src = (b*TT + t)*(KH/4) + h*(KK/4) + cc;
            skd[v] = k4[src];
            svd[v] = v4[src];
        }
    }

    float q[KK];
    {
        const float4* q4 = (const float4*)(g_q + (b*TT + i)*KH + h*KK);
        #pragma unroll
        for (int c = 0; c < KK/4; c++) {
            float4 t = q4[c];
            q[c*4] = t.x; q[c*4+1] = t.y; q[c*4+2] = t.z; q[c*4+3] = t.w;
        }
    }
    __syncthreads();

    const float scale = rsqrtf((float)KK);
    float mrun = -1e30f, denom = 0.f;
    float acc[KK];
    #pragma unroll
    for (int c = 0; c < KK; c++) acc[c] = 0.f;

    const float4* sk4 = (const float4*)sk;
    const float4* sv4 = (const float4*)sv;
    int j0 = half * 64;

    for (int jj = 0; jj < 64; jj++) {
        int j = j0 + jj;
        float l = 0.f;
        #pragma unroll
        for (int c4 = 0; c4 < KK/4; c4++) {
            float4 kv = sk4[j*(KK/4) + c4];
            int c = c4*4;
            l = fmaf(q[c], kv.x, fmaf(q[c+1], kv.y, fmaf(q[c+2], kv.z, fmaf(q[c+3], kv.w, l))));
        }
        l = (j == i) ? -1e30f : l * scale;   // self masked out
        float mn   = fmaxf(mrun, l);
        float corr = __expf(mrun - mn);
        float p    = __expf(l - mn);
        denom = denom * corr + p;
        #pragma unroll
        for (int c4 = 0; c4 < KK/4; c4++) {
            float4 vv = sv4[j*(KK/4) + c4];
            int c = c4*4;
            acc[c]   = fmaf(acc[c],   corr, p * vv.x);
            acc[c+1] = fmaf(acc[c+1], corr, p * vv.y);
            acc[c+2] = fmaf(acc[c+2], corr, p * vv.z);
            acc[c+3] = fmaf(acc[c+3], corr, p * vv.w);
        }
        mrun = mn;
    }

    __syncthreads();              // everyone done reading sk
    if (half == 1) {              // stash second half's partials (reuse sk)
        sm2[i] = mrun;
        sd2[i] = denom;
        #pragma unroll
        for (int c = 0; c < KK; c++) sk[i*KK + c] = acc[c];
    }
    __syncthreads();

    if (half == 0) {              // merge and write out
        float m1 = sm2[i], d1 = sd2[i];
        float mn = fmaxf(mrun, m1);
        float e0 = __expf(mrun - mn), e1 = __expf(m1 - mn);
        float inv = 1.f / (denom * e0 + d1 * e1);
        float* op = g_att + (b*TT + i)*KH + h*KK;
        #pragma unroll
        for (int c = 0; c < KK; c++)
            op[c] = (acc[c]*e0 + sk[i*KK + c]*e1) * inv - sv[i*KK + c];
    }
}

// ---------------------------------------------------------------------------
// Kernel 3: MLP. x = [att | state] (160) -> relu(x@W1+b1) -> relu(@W2+b2) -> @Wo+bo
// 16 rows per block, 256 threads = one per hidden unit. Inner dim unrolled x4
// with float4 activation broadcasts to keep issue slots on the FMA pipe.
// ---------------------------------------------------------------------------
__global__ void __launch_bounds__(256,2) mlp_kernel(
        const float* __restrict__ state,
        const float* __restrict__ W1, const float* __restrict__ b1,
        const float* __restrict__ W2, const float* __restrict__ b2,
        const float* __restrict__ Wo, const float* __restrict__ bo,
        float* __restrict__ out) {
    const int R = 16;
    __shared__ float xs[R][DIN];   // 10KB
    __shared__ float hs[R][HID];   // 16KB
    int row0 = blockIdx.x * R;
    int tid  = threadIdx.x;        // 256

    {
        const float4* a4 = (const float4*)(g_att + row0*KH);
        #pragma unroll
        for (int it = 0; it < (R*KH/4)/256; it++) {
            int v = tid + it*256;          // float4 idx over R*128 floats
            int r = v >> 5, cc = v & 31;
            float4 t = a4[v];
            xs[r][cc*4] = t.x; xs[r][cc*4+1] = t.y; xs[r][cc*4+2] = t.z; xs[r][cc*4+3] = t.w;
        }
        const float4* s4 = (const float4*)(state + row0*KK);
        if (tid < R*KK/4) {
            int r = tid >> 3, cc = tid & 7;
            float4 t = s4[tid];
            xs[r][KH + cc*4] = t.x; xs[r][KH + cc*4+1] = t.y;
            xs[r][KH + cc*4+2] = t.z; xs[r][KH + cc*4+3] = t.w;
        }
    }
    __syncthreads();

    // layer 1: thread = hidden unit `tid`, all 16 rows
    float acc[R];
    {
        float bias = b1[tid];
        #pragma unroll
        for (int r = 0; r < R; r++) acc[r] = bias;
        #pragma unroll 4
        for (int i = 0; i < DIN; i += 4) {
            float w0 = W1[(i+0)*HID + tid];
            float w1 = W1[(i+1)*HID + tid];
            float w2 = W1[(i+2)*HID + tid];
            float w3 = W1[(i+3)*HID + tid];
            #pragma unroll
            for (int r = 0; r < R; r++) {
                float4 x = *(const float4*)&xs[r][i];
                acc[r] = fmaf(x.x, w0, fmaf(x.y, w1, fmaf(x.z, w2, fmaf(x.w, w3, acc[r]))));
            }
        }
        #pragma unroll
        for (int r = 0; r < R; r++) hs[r][tid] = fmaxf(acc[r], 0.f);
    }
    __syncthreads();

    // layer 2
    {
        float bias = b2[tid];
        #pragma unroll
        for (int r = 0; r < R; r++) acc[r] = bias;
        #pragma unroll 4
        for (int i = 0; i < HID; i += 4) {
            float w0 = W2[(i+0)*HID + tid];
            float w1 = W2[(i+1)*HID + tid];
            float w2 = W2[(i+2)*HID + tid];
            float w3 = W2[(i+3)*HID + tid];
            #pragma unroll
            for (int r = 0; r < R; r++) {
                float4 x = *(const float4*)&hs[r][i];
                acc[r] = fmaf(x.x, w0, fmaf(x.y, w1, fmaf(x.z, w2, fmaf(x.w, w3, acc[r]))));
            }
        }
    }
    __syncthreads();

    // output: relu(h2) * Wo[tid], then row-wise reduce over the 256 units
    float wo = Wo[tid];
    #pragma unroll
    for (int r = 0; r < R; r++) hs[r][tid] = fmaxf(acc[r], 0.f) * wo;
    __syncthreads();

    int w = tid >> 5, lane = tid & 31;
    float bov = bo[0];
    #pragma unroll
    for (int rr = 0; rr < 2; rr++) {
        int r = w*2 + rr;
        float s = 0.f;
        #pragma unroll
        for (int c = 0; c < HID/32; c++) s += hs[r][lane + c*32];
        #pragma unroll
        for (int off = 16; off; off >>= 1)
            s += __shfl_xor_sync(0xffffffffu, s, off);
        if (lane == 0) out[row0 + r] = s + bov;
    }
}

// ---------------------------------------------------------------------------
extern "C" void kernel_launch(void* const* d_in, const int* in_sizes, int n_in,
                              void* d_out, int out_size) {
    const float* state = (const float*)d_in[0];
    const float* Wq    = (const float*)d_in[1];
    const float* Wk    = (const float*)d_in[2];
    const float* Wv    = (const float*)d_in[3];
    const float* W1    = (const float*)d_in[4];
    const float* b1    = (const float*)d_in[5];
    const float* W2    = (const float*)d_in[6];
    const float* b2    = (const float*)d_in[7];
    const float* Wo    = (const float*)d_in[8];
    const float* bo    = (const float*)d_in[9];
    float* out = (float*)d_out;

    proj_kernel<<<dim3(BB, 3, 4), 128>>>(state, Wq, Wk, Wv);
    attn_kernel<<<dim3(BB, HH), 256>>>();
    mlp_kernel<<<(BB*TT)/16, 256>>>(state, W1, b1, W2, b2, Wo, bo, out);
}